// round 14
// baseline (speedup 1.0000x reference)
#include <cuda_runtime.h>
#include <cstdint>
#include <cstddef>

// ============================================================================
// Conductor: 2-layer LSTM (B=1024, H=1024, 4 steps, const input z) + Linear.
// sm_100 legacy mma.sync tf32 path.
//
// Round 14: R5 geometry (CTA 128x128, 8 warps 64x32, 256 thr, 3-stage,
// 2 CTA/SM -- measured best 884.7us, cell-epilogue free) with the scalar-LDS
// fragment loads replaced by ldmatrix.x4 (24 LDSM vs 96 LDS per K-tile/warp)
// + the R12-proven shuffle CELL epilogue (permuted lane-private c).
// ============================================================================

#define B_   1024
#define H_   1024
#define H4_  4096
#define KDIM 1024

#define BM 128
#define BN 128
#define NT 256                               // threads per CTA
#define NS 3
#define STAGE_F ((BM + BN) * 32)             // 8192 floats (A 4096 + B 4096)
#define STAGE_BYTES (STAGE_F * 4)            // 32768
#define SMEM_TOTAL (NS * STAGE_BYTES)        // 98304 bytes
#define SH_PAD 36                            // h staging row stride (floats)

// ---------------- device scratch (static; no runtime allocation) ------------
__device__ float g_h0[2][B_ * H_];
__device__ float g_h1[2][B_ * H_];
__device__ float g_c0p[B_ * H_];             // permuted [cta][k][tid]
__device__ float g_c1p[B_ * H_];
__device__ float g_G0x[(size_t)B_ * H4_];
__device__ float g_hist[(size_t)B_ * 4 * H_];                   // [b][step][h]
__device__ float g_Wr[(size_t)4 * H4_ * H_ + (size_t)H_ * H_];  // rounded weights
__device__ float g_bs0[H4_];
__device__ float g_bs1[H4_];

// ---------------- helpers ----------------------------------------------------
__device__ __forceinline__ float rnd_tf32(float x) {
    uint32_t u;
    asm("cvt.rna.tf32.f32 %0, %1;" : "=r"(u) : "f"(x));
    return __uint_as_float(u);
}

__device__ __forceinline__ void cp16(void* sm, const void* gm) {
    uint32_t s = (uint32_t)__cvta_generic_to_shared(sm);
    asm volatile("cp.async.cg.shared.global [%0], [%1], 16;" :: "r"(s), "l"(gm) : "memory");
}

__device__ __forceinline__ void mma8(float* d, const uint32_t* a, const uint32_t* b) {
    asm volatile(
        "mma.sync.aligned.m16n8k8.row.col.f32.tf32.tf32.f32 "
        "{%0,%1,%2,%3},{%4,%5,%6,%7},{%8,%9},{%0,%1,%2,%3};"
        : "+f"(d[0]), "+f"(d[1]), "+f"(d[2]), "+f"(d[3])
        : "r"(a[0]), "r"(a[1]), "r"(a[2]), "r"(a[3]), "r"(b[0]), "r"(b[1]));
}

__device__ __forceinline__ void ldsm4(uint32_t* r, uint32_t addr) {
    asm volatile(
        "ldmatrix.sync.aligned.m8n8.x4.shared.b16 {%0,%1,%2,%3}, [%4];"
        : "=r"(r[0]), "=r"(r[1]), "=r"(r[2]), "=r"(r[3]) : "r"(addr));
}

__device__ __forceinline__ int swz(int row, int grp) {
    return row * 32 + (((grp) ^ (row & 7)) << 2);
}

__device__ __forceinline__ float sigmf(float x) { return 1.f / (1.f + __expf(-x)); }

// ---------------- weight rounding + gate-interleave permutation --------------
struct RoundArgs {
    const float4* src[5];
    float4*       dst[5];
};

__global__ void round_all_kernel(RoundArgs a) {
    int i = blockIdx.x * blockDim.x + threadIdx.x;
    const int WSEG = (H4_ * H_) / 4;
    int seg;
    size_t soff, doff;
    if (i < 4 * WSEG) {
        seg = i / WSEG;
        int off = i % WSEG;
        int rp = off >> 8;
        int c4 = off & 255;
        int j = rp >> 2, g = rp & 3;
        soff = (size_t)(g * 1024 + j) * 256 + c4;
        doff = off;
    } else {
        seg = 4;
        int off = i - 4 * WSEG;
        if (off >= (H_ * H_) / 4) return;
        soff = doff = off;
    }
    float4 v = a.src[seg][soff];
    v.x = rnd_tf32(v.x); v.y = rnd_tf32(v.y); v.z = rnd_tf32(v.z); v.w = rnd_tf32(v.w);
    a.dst[seg][doff] = v;
}

__global__ void bias_perm_kernel(const float* __restrict__ bi0, const float* __restrict__ bh0,
                                 const float* __restrict__ bi1, const float* __restrict__ bh1,
                                 float* __restrict__ bs0, float* __restrict__ bs1) {
    int t = blockIdx.x * blockDim.x + threadIdx.x;
    int j = t >> 2, g = t & 3;
    int s = g * 1024 + j;
    bs0[t] = bi0[s] + bh0[s];
    bs1[t] = bi1[s] + bh1[s];
}

__global__ void init_h_kernel(const float4* __restrict__ z4,
                              float4* __restrict__ h0, float4* __restrict__ h1) {
    int i = blockIdx.x * blockDim.x + threadIdx.x;
    float4 v = z4[i];
    v.x = rnd_tf32(v.x); v.y = rnd_tf32(v.y); v.z = rnd_tf32(v.z); v.w = rnd_tf32(v.w);
    h0[i] = v; h1[i] = v;
}

// c_perm[cta][k][tid] = z[m][j] with the exact CELL-epilogue lane mapping.
// CELL grid is (32, 8): cta = by*32 + bx; k = mi*4 + ni (16 per thread).
__global__ void init_cperm_kernel(const float* __restrict__ z,
                                  float* __restrict__ c0p, float* __restrict__ c1p) {
    const int blk  = blockIdx.x;            // cta*16 + k
    const int cta  = blk >> 4;
    const int k    = blk & 15;
    const int tid  = threadIdx.x;
    const int lane = tid & 31;
    const int warp = tid >> 5;              // 0..7
    const int mi = k >> 2, ni = k & 3;
    const int bx = cta & 31, by = cta >> 5; // grid (32, 8)
    const int wm = (warp & 1) * 64, wn = (warp >> 1) * 32;
    const int er = lane >> 2;
    const int m  = by * 128 + wm + mi * 16 + er + 8 * (lane & 1);
    const int ul = ((wn + ni * 8) >> 2) + ((lane >> 1) & 1);
    const int j  = bx * 32 + ul;
    float v = z[(size_t)m * H_ + j];
    size_t o = (size_t)blk * NT + tid;
    c0p[o] = v;
    c1p[o] = v;
}

// ---------------- fused tf32 GEMM (+optional LSTM cell epilogue) -------------
// CTA 128x128, K-tiles of 32, 3-stage cp.async, 8 warps (warp tile 64x32),
// 256 threads, 2 CTAs/SM, ldmatrix fragment loads.
template <bool PAIR2, bool CADD, bool BIAS, bool CELL>
__global__ void __launch_bounds__(NT, 2)
gemm_f(const float* __restrict__ A1, const float* __restrict__ W1,
       const float* __restrict__ A2, const float* __restrict__ W2,
       const float* __restrict__ Cadd, const float* __restrict__ bias,
       float* __restrict__ C, int ldc,
       float* __restrict__ cperm, float* __restrict__ h_out,
       float* __restrict__ hist, int step) {
    extern __shared__ float sm[];   // NS * 8192 floats

    const int tid  = threadIdx.x;
    const int lane = tid & 31;
    const int warp = tid >> 5;               // 0..7
    const int wm   = (warp & 1) * 64;        // M offset (2)
    const int wn   = (warp >> 1) * 32;       // N offset (4)
    const int mBase = blockIdx.y * BM;
    const int nBase = blockIdx.x * BN;

    const float* Ae1 = A1 + (size_t)mBase * KDIM;
    const float* We1 = W1 + (size_t)nBase * KDIM;
    const float* Ae2 = PAIR2 ? A2 + (size_t)mBase * KDIM : nullptr;
    const float* We2 = PAIR2 ? W2 + (size_t)nBase * KDIM : nullptr;

    const int g    = tid & 7;
    const int rowb = tid >> 3;               // 0..31
    const int goff = g * 4;

    float acc[4][4][4];
#pragma unroll
    for (int mi = 0; mi < 4; mi++)
#pragma unroll
        for (int ni = 0; ni < 4; ni++)
#pragma unroll
            for (int k = 0; k < 4; k++) acc[mi][ni][k] = 0.f;

    const int T = PAIR2 ? 64 : 32;

    auto load_tile = [&](int tt) {
        const float* Ap = (!PAIR2 || tt < 32) ? Ae1 : Ae2;
        const float* Wp = (!PAIR2 || tt < 32) ? We1 : We2;
        const int k0 = (tt & 31) * 32 + goff;
        float* As = sm + (tt % NS) * STAGE_F;
        float* Bs = As + BM * 32;
#pragma unroll
        for (int i = 0; i < 4; i++) {
            int r = rowb + i * 32;
            cp16(As + swz(r, g), Ap + (size_t)r * KDIM + k0);
            cp16(Bs + swz(r, g), Wp + (size_t)r * KDIM + k0);
        }
        asm volatile("cp.async.commit_group;" ::: "memory");
    };

    load_tile(0);
    load_tile(1);

    // per-lane ldmatrix row bases (bytes within tile)
    const uint32_t sm32  = (uint32_t)__cvta_generic_to_shared(sm);
    const int l7  = lane & 7;
    const int l8  = (lane >> 3) & 1;
    const int l16 = lane >> 4;
    const uint32_t arowB = (uint32_t)(wm + l7 + 8 * l8) * 128;       // + mi*2048
    const uint32_t browB = (uint32_t)(wn + l7 + 8 * l8) * 128;       // ni pair 0/1
    // pair 1 (+16 rows) = browB + 2048

    for (int t = 0; t < T; ++t) {
        asm volatile("cp.async.wait_group 1;" ::: "memory");
        __syncthreads();                     // all warps done reading stage (t-1)%NS

        if (t + 2 < T) load_tile(t + 2);
        else           asm volatile("cp.async.commit_group;" ::: "memory");

        const uint32_t aBase = sm32 + (uint32_t)((t % NS) * STAGE_BYTES);
        const uint32_t bBase = aBase + 16384;
#pragma unroll
        for (int ks = 0; ks < 4; ++ks) {
            const uint32_t xt = (uint32_t)(((2 * ks + l16) ^ l7) << 4);
            uint32_t bf0[4], bf1[4];
            ldsm4(bf0, bBase + browB + xt);            // (ni0,g0)(ni1,g0)(ni0,g1)(ni1,g1)
            ldsm4(bf1, bBase + browB + 2048 + xt);     // ni2/ni3
            uint32_t af[4][4];
#pragma unroll
            for (int mi = 0; mi < 4; mi++)
                ldsm4(af[mi], aBase + arowB + mi * 2048 + xt);

            uint32_t bf[4][2];
            bf[0][0] = bf0[0]; bf[1][0] = bf0[1]; bf[0][1] = bf0[2]; bf[1][1] = bf0[3];
            bf[2][0] = bf1[0]; bf[3][0] = bf1[1]; bf[2][1] = bf1[2]; bf[3][1] = bf1[3];
#pragma unroll
            for (int mi = 0; mi < 4; mi++)
#pragma unroll
                for (int ni = 0; ni < 4; ni++)
                    mma8(acc[mi][ni], af[mi], bf[ni]);
        }
    }

    // ---- epilogue ----
    const int er = lane >> 2, ec = (lane & 3) * 2;

    if (!CELL) {
#pragma unroll
        for (int mi = 0; mi < 4; mi++) {
#pragma unroll
            for (int ni = 0; ni < 4; ni++) {
                const int row0 = mBase + wm + mi * 16 + er;
                const int col  = nBase + wn + ni * 8 + ec;
                float b0 = 0.f, b1 = 0.f;
                if (BIAS) { b0 = bias[col]; b1 = bias[col + 1]; }
                float2 o0 = make_float2(acc[mi][ni][0] + b0, acc[mi][ni][1] + b1);
                float2 o1 = make_float2(acc[mi][ni][2] + b0, acc[mi][ni][3] + b1);
                if (CADD) {
                    float2 a0 = *(const float2*)(Cadd + (size_t)row0 * ldc + col);
                    float2 a1 = *(const float2*)(Cadd + (size_t)(row0 + 8) * ldc + col);
                    o0.x += a0.x; o0.y += a0.y; o1.x += a1.x; o1.y += a1.y;
                }
                *(float2*)(C + (size_t)row0 * ldc + col)       = o0;
                *(float2*)(C + (size_t)(row0 + 8) * ldc + col) = o1;
            }
        }
        return;
    }

    // CELL epilogue: shuffle-assemble gate quadruples, lane-private c update,
    // single smem pass for h.
    __syncthreads();                  // all warps out of the mainloop stages
    float* SH = sm;                   // 128 x SH_PAD floats (18.4 KB, over stage0)

    const int  odd  = lane & 1;
    const int  ubit = (lane >> 1) & 1;
    float* cp = cperm + ((size_t)(blockIdx.y * gridDim.x + blockIdx.x) * 16) * NT + tid;

#pragma unroll
    for (int mi = 0; mi < 4; mi++) {
#pragma unroll
        for (int ni = 0; ni < 4; ni++) {
            const int colG = nBase + wn + ni * 8 + ec;
            float v0 = acc[mi][ni][0], v1 = acc[mi][ni][1];
            float v2 = acc[mi][ni][2], v3 = acc[mi][ni][3];
            if (BIAS) {
                float b0 = bias[colG], b1 = bias[colG + 1];
                v0 += b0; v1 += b1; v2 += b0; v3 += b1;
            }
            if (CADD) {
                const int gr0 = mBase + wm + mi * 16 + er;
                float2 a0 = *(const float2*)(Cadd + (size_t)gr0 * ldc + colG);
                float2 a1 = *(const float2*)(Cadd + (size_t)(gr0 + 8) * ldc + colG);
                v0 += a0.x; v1 += a0.y; v2 += a1.x; v3 += a1.y;
            }
            // exchange with partner lane (lane^1): even keeps row er, odd row er+8
            float s0 = odd ? v0 : v2;
            float s1 = odd ? v1 : v3;
            float r0 = __shfl_xor_sync(0xFFFFFFFFu, s0, 1);
            float r1 = __shfl_xor_sync(0xFFFFFFFFu, s1, 1);
            float gi = odd ? r0 : v0;
            float gf = odd ? r1 : v1;
            float gg = odd ? v2 : r0;
            float go = odd ? v3 : r1;

            float cin = cp[(mi * 4 + ni) * NT];           // coalesced
            float cc  = sigmf(gf) * cin + sigmf(gi) * tanhf(gg);
            float hh  = rnd_tf32(sigmf(go) * tanhf(cc));
            cp[(mi * 4 + ni) * NT] = cc;                  // coalesced, in-place

            const int row_l = wm + mi * 16 + er + 8 * odd;
            const int ul    = ((wn + ni * 8) >> 2) + ubit;
            SH[row_l * SH_PAD + ul] = hh;
        }
    }
    __syncthreads();

    // writeback h (+hist): thread -> (row = tid>>1, half = tid&1), 4 float4 each
    {
        const int row  = tid >> 1;
        const int half = tid & 1;
        const int m    = mBase + row;
        const int j0   = (nBase >> 2) + half * 16;
        const float* shr = SH + row * SH_PAD + half * 16;
        float* hrow = h_out + (size_t)m * H_ + j0;
        float* trow = hist ? hist + ((size_t)m * 4 + step) * H_ + j0 : nullptr;
#pragma unroll
        for (int k = 0; k < 4; ++k) {
            float4 v = *(const float4*)(shr + 4 * k);
            *(float4*)(hrow + 4 * k) = v;
            if (trow) *(float4*)(trow + 4 * k) = v;
        }
    }
}

// ---------------- host launcher ---------------------------------------------
extern "C" void kernel_launch(void* const* d_in, const int* in_sizes, int n_in,
                              void* d_out, int out_size) {
    const float* z     = (const float*)d_in[0];
    const float* W_ih0 = (const float*)d_in[1];
    const float* W_hh0 = (const float*)d_in[2];
    const float* b_ih0 = (const float*)d_in[3];
    const float* b_hh0 = (const float*)d_in[4];
    const float* W_ih1 = (const float*)d_in[5];
    const float* W_hh1 = (const float*)d_in[6];
    const float* b_ih1 = (const float*)d_in[7];
    const float* b_hh1 = (const float*)d_in[8];
    const float* W_lin = (const float*)d_in[9];
    const float* b_lin = (const float*)d_in[10];

    float *h0, *h1, *c0p, *c1p, *G0x, *hist, *Wr, *bs0, *bs1;
    cudaGetSymbolAddress((void**)&h0,   g_h0);
    cudaGetSymbolAddress((void**)&h1,   g_h1);
    cudaGetSymbolAddress((void**)&c0p,  g_c0p);
    cudaGetSymbolAddress((void**)&c1p,  g_c1p);
    cudaGetSymbolAddress((void**)&G0x,  g_G0x);
    cudaGetSymbolAddress((void**)&hist, g_hist);
    cudaGetSymbolAddress((void**)&Wr,   g_Wr);
    cudaGetSymbolAddress((void**)&bs0,  g_bs0);
    cudaGetSymbolAddress((void**)&bs1,  g_bs1);

    float* h0b[2] = {h0, h0 + (size_t)B_ * H_};
    float* h1b[2] = {h1, h1 + (size_t)B_ * H_};

    float* Wih0p = Wr;
    float* Whh0p = Wr + (size_t)4 * 1024 * 1024;
    float* Wih1p = Wr + (size_t)8 * 1024 * 1024;
    float* Whh1p = Wr + (size_t)12 * 1024 * 1024;
    float* Wlinr = Wr + (size_t)16 * 1024 * 1024;

    cudaFuncSetAttribute((const void*)gemm_f<false, false, true, false>,
                         cudaFuncAttributeMaxDynamicSharedMemorySize, SMEM_TOTAL);
    cudaFuncSetAttribute((const void*)gemm_f<false, true, false, true>,
                         cudaFuncAttributeMaxDynamicSharedMemorySize, SMEM_TOTAL);
    cudaFuncSetAttribute((const void*)gemm_f<true, false, true, true>,
                         cudaFuncAttributeMaxDynamicSharedMemorySize, SMEM_TOTAL);

    // 1) round + permute weights; permuted summed biases; init state
    {
        RoundArgs ra;
        ra.src[0] = (const float4*)W_ih0; ra.dst[0] = (float4*)Wih0p;
        ra.src[1] = (const float4*)W_hh0; ra.dst[1] = (float4*)Whh0p;
        ra.src[2] = (const float4*)W_ih1; ra.dst[2] = (float4*)Wih1p;
        ra.src[3] = (const float4*)W_hh1; ra.dst[3] = (float4*)Whh1p;
        ra.src[4] = (const float4*)W_lin; ra.dst[4] = (float4*)Wlinr;
        const int total4 = 4 * (H4_ * H_) / 4 + (H_ * H_) / 4;
        round_all_kernel<<<(total4 + 255) / 256, 256>>>(ra);
    }
    bias_perm_kernel<<<H4_ / 256, 256>>>(b_ih0, b_hh0, b_ih1, b_hh1, bs0, bs1);
    init_h_kernel<<<(B_ * H_ / 4) / 256, 256>>>((const float4*)z,
                                                (float4*)h0b[0], (float4*)h1b[0]);
    init_cperm_kernel<<<256 * 16, NT>>>(z, c0p, c1p);

    // 2) G0x = rnd(z) @ W_ih0p^T + bs0
    dim3 gBig(H4_ / BN, B_ / BM);      // (32, 8) -> 256 CTAs, 2/SM, single wave
    gemm_f<false, false, true, false><<<gBig, NT, SMEM_TOTAL>>>(
        h0b[0], Wih0p, nullptr, nullptr, nullptr, bs0, G0x, H4_,
        nullptr, nullptr, nullptr, 0);

    // 3) recurrence: 2 fused GEMM+cell launches per step
    for (int s = 0; s < 4; ++s) {
        const int in = s & 1, out = in ^ 1;
        gemm_f<false, true, false, true><<<gBig, NT, SMEM_TOTAL>>>(
            h0b[in], Whh0p, nullptr, nullptr, G0x, nullptr, nullptr, H4_,
            c0p, h0b[out], nullptr, s);
        gemm_f<true, false, true, true><<<gBig, NT, SMEM_TOTAL>>>(
            h0b[out], Wih1p, h1b[in], Whh1p, nullptr, bs1, nullptr, H4_,
            c1p, h1b[out], hist, s);
    }

    // 4) out = hist @ W_lin^T + b_lin
    dim3 gOut(H_ / BN, (B_ * 4) / BM);  // (8, 32) = 256 CTAs
    gemm_f<false, false, true, false><<<gOut, NT, SMEM_TOTAL>>>(
        hist, Wlinr, nullptr, nullptr, nullptr, b_lin, (float*)d_out, H_,
        nullptr, nullptr, nullptr, 0);
}

// round 16
// speedup vs baseline: 1.8609x; 1.8609x over previous
#include <cuda_runtime.h>
#include <cuda_fp16.h>
#include <cstdint>
#include <cstddef>

// ============================================================================
// Conductor: 2-layer LSTM (B=1024, H=1024, 4 steps, const input z) + Linear.
// sm_100 legacy mma.sync path.
//
// Round 16 = fp16 kernel resubmitted verbatim (container infra failure):
// R5 kernel (measured best, 884.7us) with the GEMM datapath moved from
// tf32 m16n8k8 to fp16 m16n8k16 (SAME 11-bit mantissa, 2x K per MMA,
// half the smem bytes -> both measured limiters halve). K-tile = 64 fp16
// (128B swizzled rows: fragment indexing identical to the tf32 code).
// Weights/h/hist fp16; c, G0x, biases, accumulators, output stay fp32.
// CTA 128x128, 8 warps 64x32, 256 thr, 3-stage cp.async, 2 CTA/SM,
// LSTM cell fused in epilogue (R5's proven-free smem-staging form).
// ============================================================================

#define B_   1024
#define H_   1024
#define H4_  4096
#define KDIM 1024

#define NS 3
#define STAGE_F 8192                   // floats of smem per stage (A 16KB + B 16KB)
#define SMEM_TOTAL (NS * STAGE_F * 4)  // 98304 bytes

// ---------------- device scratch (static; no runtime allocation) ------------
__device__ __half g_h0[2][B_ * H_];
__device__ __half g_h1[2][B_ * H_];
__device__ float  g_c0[B_ * H_];
__device__ float  g_c1[B_ * H_];
__device__ float  g_G0x[(size_t)B_ * H4_];
__device__ __half g_hist[(size_t)B_ * 4 * H_];                   // [b][step][h]
__device__ __half g_Wr[(size_t)4 * H4_ * H_ + (size_t)H_ * H_];  // fp16 weights
__device__ float  g_bs0[H4_];   // permuted b_ih0+b_hh0
__device__ float  g_bs1[H4_];   // permuted b_ih1+b_hh1

// ---------------- helpers ----------------------------------------------------
__device__ __forceinline__ void cp16(void* sm, const void* gm) {
    uint32_t s = (uint32_t)__cvta_generic_to_shared(sm);
    asm volatile("cp.async.cg.shared.global [%0], [%1], 16;" :: "r"(s), "l"(gm) : "memory");
}

// fp16 MMA: D(fp32) += A(fp16) * B(fp16); A 4 regs, B 2 regs, K=16.
__device__ __forceinline__ void mma16(float* d, const uint32_t* a, const uint32_t* b) {
    asm volatile(
        "mma.sync.aligned.m16n8k16.row.col.f32.f16.f16.f32 "
        "{%0,%1,%2,%3},{%4,%5,%6,%7},{%8,%9},{%0,%1,%2,%3};"
        : "+f"(d[0]), "+f"(d[1]), "+f"(d[2]), "+f"(d[3])
        : "r"(a[0]), "r"(a[1]), "r"(a[2]), "r"(a[3]), "r"(b[0]), "r"(b[1]));
}

__device__ __forceinline__ int swz(int row, int grp) {
    // rows of 128B (32 "float" slots = 64 fp16); 8 16B groups, XOR swizzle
    return row * 32 + (((grp) ^ (row & 7)) << 2);
}

__device__ __forceinline__ float sigmf(float x) { return 1.f / (1.f + __expf(-x)); }

// ---------------- weight conversion + gate-interleave permutation -----------
// LSTM weights: dst row 4j+g = src row g*1024+j (gate order i,f,g,o). W_lin: id.
struct RoundArgs {
    const float4* src[5];
    __half*       dst[5];
};

__global__ void round_all_kernel(RoundArgs a) {
    int i = blockIdx.x * blockDim.x + threadIdx.x;
    const int WSEG = (H4_ * H_) / 4;        // 1M float4 per LSTM matrix
    int seg;
    size_t soff, doff;
    if (i < 4 * WSEG) {
        seg = i / WSEG;
        int off = i % WSEG;
        int rp = off >> 8;                  // dst row (256 float4/row)
        int c4 = off & 255;
        int j = rp >> 2, g = rp & 3;
        soff = (size_t)(g * 1024 + j) * 256 + c4;
        doff = off;
    } else {
        seg = 4;
        int off = i - 4 * WSEG;
        if (off >= (H_ * H_) / 4) return;
        soff = doff = off;
    }
    float4 v = a.src[seg][soff];
    __half2* d2 = (__half2*)(a.dst[seg] + doff * 4);
    d2[0] = __floats2half2_rn(v.x, v.y);
    d2[1] = __floats2half2_rn(v.z, v.w);
}

__global__ void bias_perm_kernel(const float* __restrict__ bi0, const float* __restrict__ bh0,
                                 const float* __restrict__ bi1, const float* __restrict__ bh1,
                                 float* __restrict__ bs0, float* __restrict__ bs1) {
    int t = blockIdx.x * blockDim.x + threadIdx.x;   // 0..4095
    int j = t >> 2, g = t & 3;
    int s = g * 1024 + j;
    bs0[t] = bi0[s] + bh0[s];
    bs1[t] = bi1[s] + bh1[s];
}

__global__ void init_kernel(const float4* __restrict__ z4,
                            __half* __restrict__ h0, float4* __restrict__ c0,
                            __half* __restrict__ h1, float4* __restrict__ c1) {
    int i = blockIdx.x * blockDim.x + threadIdx.x;
    float4 v = z4[i];
    __half2 p0 = __floats2half2_rn(v.x, v.y);
    __half2 p1 = __floats2half2_rn(v.z, v.w);
    ((__half2*)(h0 + i * 4))[0] = p0; ((__half2*)(h0 + i * 4))[1] = p1;
    ((__half2*)(h1 + i * 4))[0] = p0; ((__half2*)(h1 + i * 4))[1] = p1;
    c0[i] = v;  c1[i] = v;
}

// ---------------- fused fp16 GEMM (+optional LSTM cell epilogue) -------------
// acc[M,N] = sum_pairs A@W^T (+bias)(+Cadd);  A:[M,1024] fp16 rm, W fp16 rm.
// CELL: gate-interleaved cols (4j+g); epilogue computes the cell, writes
// h_out (fp16), c_out (fp32), hist (fp16). Otherwise writes C (fp32).
// CTA 128x128, K-tiles of 64 fp16, 3-stage cp.async, 8 warps (64x32).
template <bool PAIR2, bool CADD, bool BIAS, bool CELL>
__global__ void __launch_bounds__(256, 2)
gemm_f(const __half* __restrict__ A1, const __half* __restrict__ W1,
       const __half* __restrict__ A2, const __half* __restrict__ W2,
       const float* __restrict__ Cadd, const float* __restrict__ bias,
       float* __restrict__ C, int ldc,
       const float* __restrict__ c_in, float* __restrict__ c_out,
       __half* __restrict__ h_out, __half* __restrict__ hist, int step) {
    extern __shared__ float sm[];   // NS * 8192 floats

    const int tid  = threadIdx.x;
    const int lane = tid & 31;
    const int warp = tid >> 5;
    const int wm   = (warp & 1) * 64;
    const int wn   = (warp >> 1) * 32;
    const int mBase = blockIdx.y * 128;
    const int nBase = blockIdx.x * 128;

    const __half* Ae1 = A1 + (size_t)mBase * KDIM;
    const __half* We1 = W1 + (size_t)nBase * KDIM;
    const __half* Ae2 = PAIR2 ? A2 + (size_t)mBase * KDIM : nullptr;
    const __half* We2 = PAIR2 ? W2 + (size_t)nBase * KDIM : nullptr;

    const int g    = tid & 7;
    const int rowb = tid >> 3;
    int soff[4];
#pragma unroll
    for (int i = 0; i < 4; i++) soff[i] = swz(rowb + i * 32, g);

    float acc[4][4][4];
#pragma unroll
    for (int mi = 0; mi < 4; mi++)
#pragma unroll
        for (int ni = 0; ni < 4; ni++)
#pragma unroll
            for (int k = 0; k < 4; k++) acc[mi][ni][k] = 0.f;

    const int T = PAIR2 ? 32 : 16;          // K-tiles of 64 fp16

    auto load_tile = [&](int tt) {
        const __half* Ap = (!PAIR2 || tt < 16) ? Ae1 : Ae2;
        const __half* Wp = (!PAIR2 || tt < 16) ? We1 : We2;
        const int k0 = (tt & 15) * 64 + g * 8;       // fp16 elements
        float* As = sm + (tt % NS) * STAGE_F;
        float* Bs = As + 4096;
#pragma unroll
        for (int i = 0; i < 4; i++) {
            int r = rowb + i * 32;
            cp16(As + soff[i], Ap + (size_t)r * KDIM + k0);
            cp16(Bs + soff[i], Wp + (size_t)r * KDIM + k0);
        }
        asm volatile("cp.async.commit_group;" ::: "memory");
    };

    load_tile(0);
    load_tile(1);

    const int fr = lane >> 2, fc = lane & 3;

    for (int t = 0; t < T; ++t) {
        if (t == T - 1) asm volatile("cp.async.wait_group 0;" ::: "memory");
        else            asm volatile("cp.async.wait_group 1;" ::: "memory");
        __syncthreads();

        const float* As = sm + (t % NS) * STAGE_F;
        const float* Bs = As + 4096;
#pragma unroll
        for (int ks = 0; ks < 4; ++ks) {             // 4 x K=16 per 64-elem tile
            const int g0 = ks * 2, g1 = g0 + 1;
            uint32_t af[4][4];
#pragma unroll
            for (int mi = 0; mi < 4; mi++) {
                int r0 = wm + mi * 16 + fr;
                int r1 = r0 + 8;
                af[mi][0] = __float_as_uint(As[swz(r0, g0) + fc]);
                af[mi][1] = __float_as_uint(As[swz(r1, g0) + fc]);
                af[mi][2] = __float_as_uint(As[swz(r0, g1) + fc]);
                af[mi][3] = __float_as_uint(As[swz(r1, g1) + fc]);
            }
            uint32_t bf[4][2];
#pragma unroll
            for (int ni = 0; ni < 4; ni++) {
                int rn = wn + ni * 8 + fr;
                bf[ni][0] = __float_as_uint(Bs[swz(rn, g0) + fc]);
                bf[ni][1] = __float_as_uint(Bs[swz(rn, g1) + fc]);
            }
#pragma unroll
            for (int mi = 0; mi < 4; mi++)
#pragma unroll
                for (int ni = 0; ni < 4; ni++)
                    mma16(acc[mi][ni], af[mi], bf[ni]);
        }

        if (t + 2 < T) load_tile(t + 2);
    }

    // ---- epilogue ----
    const int er = lane >> 2, ec = (lane & 3) * 2;

    if (!CELL) {
#pragma unroll
        for (int mi = 0; mi < 4; mi++) {
#pragma unroll
            for (int ni = 0; ni < 4; ni++) {
                const int row0 = mBase + wm + mi * 16 + er;
                const int col  = nBase + wn + ni * 8 + ec;
                float b0 = 0.f, b1 = 0.f;
                if (BIAS) { b0 = bias[col]; b1 = bias[col + 1]; }
                float2 o0 = make_float2(acc[mi][ni][0] + b0, acc[mi][ni][1] + b1);
                float2 o1 = make_float2(acc[mi][ni][2] + b0, acc[mi][ni][3] + b1);
                if (CADD) {
                    float2 a0 = *(const float2*)(Cadd + (size_t)row0 * ldc + col);
                    float2 a1 = *(const float2*)(Cadd + (size_t)(row0 + 8) * ldc + col);
                    o0.x += a0.x; o0.y += a0.y; o1.x += a1.x; o1.y += a1.y;
                }
                *(float2*)(C + (size_t)row0 * ldc + col)       = o0;
                *(float2*)(C + (size_t)(row0 + 8) * ldc + col) = o1;
            }
        }
        return;
    }

    // CELL epilogue: stage gates to smem (stride 132), then compute LSTM cell.
    __syncthreads();                     // pipeline smem -> staging reuse
    float* S = sm;                       // 128 x 132
#pragma unroll
    for (int mi = 0; mi < 4; mi++) {
#pragma unroll
        for (int ni = 0; ni < 4; ni++) {
            const int r0  = wm + mi * 16 + er;
            const int col = wn + ni * 8 + ec;
            float b0 = 0.f, b1 = 0.f;
            if (BIAS) { b0 = bias[nBase + col]; b1 = bias[nBase + col + 1]; }
            float v0 = acc[mi][ni][0] + b0, v1 = acc[mi][ni][1] + b1;
            float v2 = acc[mi][ni][2] + b0, v3 = acc[mi][ni][3] + b1;
            if (CADD) {
                const int gr0 = mBase + r0;
                float2 a0 = *(const float2*)(Cadd + (size_t)gr0 * ldc + nBase + col);
                float2 a1 = *(const float2*)(Cadd + (size_t)(gr0 + 8) * ldc + nBase + col);
                v0 += a0.x; v1 += a0.y; v2 += a1.x; v3 += a1.y;
            }
            S[r0 * 132 + col]           = v0;
            S[r0 * 132 + col + 1]       = v1;
            S[(r0 + 8) * 132 + col]     = v2;
            S[(r0 + 8) * 132 + col + 1] = v3;
        }
    }
    __syncthreads();

    const int mg = tid >> 3;             // 0..31 -> rows 4mg..4mg+3
    const int jg = tid & 7;              // 0..7  -> local j units jg*4..+3
    const int j0 = (nBase >> 2) + jg * 4;
#pragma unroll
    for (int r = 0; r < 4; ++r) {
        const int row = mg * 4 + r;
        const int m   = mBase + row;
        const float4* gp = (const float4*)&S[row * 132 + jg * 16];
        float4 q0 = gp[0], q1 = gp[1], q2 = gp[2], q3 = gp[3];
        float4 cin = *(const float4*)&c_in[(size_t)m * H_ + j0];

        float4 cc, hh;
        cc.x = sigmf(q0.y) * cin.x + sigmf(q0.x) * tanhf(q0.z);
        cc.y = sigmf(q1.y) * cin.y + sigmf(q1.x) * tanhf(q1.z);
        cc.z = sigmf(q2.y) * cin.z + sigmf(q2.x) * tanhf(q2.z);
        cc.w = sigmf(q3.y) * cin.w + sigmf(q3.x) * tanhf(q3.z);
        hh.x = sigmf(q0.w) * tanhf(cc.x);
        hh.y = sigmf(q1.w) * tanhf(cc.y);
        hh.z = sigmf(q2.w) * tanhf(cc.z);
        hh.w = sigmf(q3.w) * tanhf(cc.w);

        *(float4*)&c_out[(size_t)m * H_ + j0] = cc;
        __half2 p0 = __floats2half2_rn(hh.x, hh.y);
        __half2 p1 = __floats2half2_rn(hh.z, hh.w);
        __half2* hp = (__half2*)(h_out + (size_t)m * H_ + j0);
        hp[0] = p0; hp[1] = p1;
        if (hist) {
            __half2* tp = (__half2*)(hist + ((size_t)m * 4 + step) * H_ + j0);
            tp[0] = p0; tp[1] = p1;
        }
    }
}

// ---------------- host launcher ---------------------------------------------
extern "C" void kernel_launch(void* const* d_in, const int* in_sizes, int n_in,
                              void* d_out, int out_size) {
    const float* z     = (const float*)d_in[0];
    const float* W_ih0 = (const float*)d_in[1];
    const float* W_hh0 = (const float*)d_in[2];
    const float* b_ih0 = (const float*)d_in[3];
    const float* b_hh0 = (const float*)d_in[4];
    const float* W_ih1 = (const float*)d_in[5];
    const float* W_hh1 = (const float*)d_in[6];
    const float* b_ih1 = (const float*)d_in[7];
    const float* b_hh1 = (const float*)d_in[8];
    const float* W_lin = (const float*)d_in[9];
    const float* b_lin = (const float*)d_in[10];

    __half *h0, *h1, *hist, *Wr;
    float *c0, *c1, *G0x, *bs0, *bs1;
    cudaGetSymbolAddress((void**)&h0,   g_h0);
    cudaGetSymbolAddress((void**)&h1,   g_h1);
    cudaGetSymbolAddress((void**)&c0,   g_c0);
    cudaGetSymbolAddress((void**)&c1,   g_c1);
    cudaGetSymbolAddress((void**)&G0x,  g_G0x);
    cudaGetSymbolAddress((void**)&hist, g_hist);
    cudaGetSymbolAddress((void**)&Wr,   g_Wr);
    cudaGetSymbolAddress((void**)&bs0,  g_bs0);
    cudaGetSymbolAddress((void**)&bs1,  g_bs1);

    __half* h0b[2] = {h0, h0 + (size_t)B_ * H_};
    __half* h1b[2] = {h1, h1 + (size_t)B_ * H_};

    __half* Wih0p = Wr;
    __half* Whh0p = Wr + (size_t)4 * 1024 * 1024;
    __half* Wih1p = Wr + (size_t)8 * 1024 * 1024;
    __half* Whh1p = Wr + (size_t)12 * 1024 * 1024;
    __half* Wlinr = Wr + (size_t)16 * 1024 * 1024;

    cudaFuncSetAttribute((const void*)gemm_f<false, false, true, false>,
                         cudaFuncAttributeMaxDynamicSharedMemorySize, SMEM_TOTAL);
    cudaFuncSetAttribute((const void*)gemm_f<false, true, false, true>,
                         cudaFuncAttributeMaxDynamicSharedMemorySize, SMEM_TOTAL);
    cudaFuncSetAttribute((const void*)gemm_f<true, false, true, true>,
                         cudaFuncAttributeMaxDynamicSharedMemorySize, SMEM_TOTAL);

    // 1) convert + permute weights to fp16; permuted summed biases; init state
    {
        RoundArgs ra;
        ra.src[0] = (const float4*)W_ih0; ra.dst[0] = Wih0p;
        ra.src[1] = (const float4*)W_hh0; ra.dst[1] = Whh0p;
        ra.src[2] = (const float4*)W_ih1; ra.dst[2] = Wih1p;
        ra.src[3] = (const float4*)W_hh1; ra.dst[3] = Whh1p;
        ra.src[4] = (const float4*)W_lin; ra.dst[4] = Wlinr;
        const int total4 = 4 * (H4_ * H_) / 4 + (H_ * H_) / 4;
        round_all_kernel<<<(total4 + 255) / 256, 256>>>(ra);
    }
    bias_perm_kernel<<<H4_ / 256, 256>>>(b_ih0, b_hh0, b_ih1, b_hh1, bs0, bs1);
    init_kernel<<<(B_ * H_ / 4) / 256, 256>>>((const float4*)z, h0b[0], (float4*)c0,
                                              h1b[0], (float4*)c1);

    // 2) G0x = fp16(z) @ W_ih0p^T + bs0   (permuted gate layout, fp32 out)
    dim3 gBig(H4_ / 128, B_ / 128);    // (32, 8) -> 256 CTAs, 2/SM, single wave
    gemm_f<false, false, true, false><<<gBig, 256, SMEM_TOTAL>>>(
        h0b[0], Wih0p, nullptr, nullptr, nullptr, bs0, G0x, H4_,
        nullptr, nullptr, nullptr, nullptr, 0);

    // 3) recurrence: 2 fused GEMM+cell launches per step
    for (int s = 0; s < 4; ++s) {
        const int in = s & 1, out = in ^ 1;
        // layer0: gates = h0 @ W_hh0p^T + G0x -> cell -> h0', c0
        gemm_f<false, true, false, true><<<gBig, 256, SMEM_TOTAL>>>(
            h0b[in], Whh0p, nullptr, nullptr, G0x, nullptr, nullptr, H4_,
            c0, c0, h0b[out], nullptr, s);
        // layer1: gates = h0' @ W_ih1p^T + h1 @ W_hh1p^T + bs1 -> cell -> h1', c1, hist
        gemm_f<true, false, true, true><<<gBig, 256, SMEM_TOTAL>>>(
            h0b[out], Wih1p, h1b[in], Whh1p, nullptr, bs1, nullptr, H4_,
            c1, c1, h1b[out], hist, s);
    }

    // 4) out = hist @ W_lin^T + b_lin   (single M=4096 GEMM, fp32 output)
    dim3 gOut(H_ / 128, (B_ * 4) / 128);  // (8, 32)
    gemm_f<false, false, true, false><<<gOut, 256, SMEM_TOTAL>>>(
        hist, Wlinr, nullptr, nullptr, nullptr, b_lin, (float*)d_out, H_,
        nullptr, nullptr, nullptr, nullptr, 0);
}